// round 11
// baseline (speedup 1.0000x reference)
#include <cuda_runtime.h>
#include <cuda_fp16.h>
#include <cstdint>
#include <math.h>

#define B_   128
#define S_   179
#define E_   1024
#define H_   16
#define D_   64
#define BS_  (B_ * S_)          // 22912
#define BH_  (B_ * H_)          // 2048
#define SP_  192                // padded sequence (12 x 16)
#define EE_  (E_ * E_)

// fp16 copies of inputs: [ x (BS_*E_) | Wq | Wk | Wv ]
__device__ __half g_fp16[(size_t)BS_ * E_ + 3 * EE_];
// projection outputs (fp16), all [bh][s][d]. Pad rows [179,192) stay zero.
__device__ __half g_Qh[BH_ * SP_ * D_];
__device__ __half g_Kh[BH_ * SP_ * D_];
__device__ __half g_Vh[BH_ * SP_ * D_];
__device__ float g_att[(size_t)BS_ * E_];

// ---------------------------------------------------------------------------
// helpers
// ---------------------------------------------------------------------------
__device__ __forceinline__ uint32_t smem_u32(const void* p) {
    uint32_t a;
    asm("{ .reg .u64 t; cvta.to.shared.u64 t, %1; cvt.u32.u64 %0, t; }" : "=r"(a) : "l"(p));
    return a;
}
__device__ __forceinline__ uint32_t pack_h2(float x, float y) {
    __half2 h = __floats2half2_rn(x, y);
    return *reinterpret_cast<uint32_t*>(&h);
}

#define LDSM_X4(r0, r1, r2, r3, addr)                                          \
    asm volatile("ldmatrix.sync.aligned.m8n8.x4.shared.b16 {%0,%1,%2,%3}, [%4];" \
                 : "=r"(r0), "=r"(r1), "=r"(r2), "=r"(r3) : "r"(addr))

#define LDSM_X4_T(r0, r1, r2, r3, addr)                                        \
    asm volatile("ldmatrix.sync.aligned.m8n8.x4.trans.shared.b16 {%0,%1,%2,%3}, [%4];" \
                 : "=r"(r0), "=r"(r1), "=r"(r2), "=r"(r3) : "r"(addr))

#define LDSM_X2_T(r0, r1, addr)                                                \
    asm volatile("ldmatrix.sync.aligned.m8n8.x2.trans.shared.b16 {%0,%1}, [%2];" \
                 : "=r"(r0), "=r"(r1) : "r"(addr))

#define MMA_F16(c, a0, a1, a2, a3, b0, b1)                                     \
    asm volatile("mma.sync.aligned.m16n8k16.row.col.f32.f16.f16.f32 "          \
        "{%0,%1,%2,%3}, {%4,%5,%6,%7}, {%8,%9}, {%0,%1,%2,%3};"                \
        : "+f"((c)[0]), "+f"((c)[1]), "+f"((c)[2]), "+f"((c)[3])               \
        : "r"(a0), "r"(a1), "r"(a2), "r"(a3), "r"(b0), "r"(b1))

#define CP16(dst, src)                                                         \
    asm volatile("cp.async.cg.shared.global [%0], [%1], 16;" :: "r"(dst), "l"(src) : "memory")
#define CP_COMMIT()  asm volatile("cp.async.commit_group;" ::: "memory")
#define CP_WAIT1()   asm volatile("cp.async.wait_group 1;" ::: "memory")
#define CP_WAIT0()   asm volatile("cp.async.wait_group 0;" ::: "memory")

// d = {hi, lo} as f16x2 (first PTX source -> upper half)
#define CVT_F16X2(d, hi, lo)                                                   \
    asm("cvt.rn.f16x2.f32 %0, %1, %2;" : "=r"(d) : "f"(hi), "f"(lo))
#define EX2_F16X2(d, s)                                                        \
    asm("ex2.approx.f16x2 %0, %1;" : "=r"(d) : "r"(s))
#define MUL_F16X2(d, a, b)                                                     \
    asm("mul.rn.f16x2 %0, %1, %2;" : "=r"(d) : "r"(a), "r"(b))

// ---------------------------------------------------------------------------
// Kernel 0: fp32 -> fp16 pre-convert. 2 float4 per thread (ILP).
// ---------------------------------------------------------------------------
__global__ __launch_bounds__(256) void cvt_fp16(
    const float* __restrict__ x,  const float* __restrict__ Wq,
    const float* __restrict__ Wk, const float* __restrict__ Wv)
{
    const int z = blockIdx.y;
    const float* src = (z == 0) ? x : ((z == 1) ? Wq : ((z == 2) ? Wk : Wv));
    const size_t cnt = (z == 0) ? (size_t)BS_ * E_ : (size_t)EE_;
    const size_t off = (z == 0) ? 0 : (size_t)BS_ * E_ + (size_t)(z - 1) * EE_;
    const size_t base = ((size_t)blockIdx.x * 512 + threadIdx.x) * 4;
#pragma unroll
    for (int r = 0; r < 2; r++) {
        const size_t i = base + (size_t)r * 1024;
        if (i < cnt) {
            float4 v = *(const float4*)(src + i);
            *(uint2*)(g_fp16 + off + i) = make_uint2(pack_h2(v.x, v.y), pack_h2(v.z, v.w));
        }
    }
}

// ---------------------------------------------------------------------------
// Kernel 1: QKV projection, fp16 MMA.  C = A @ W^T.
// CTA tile 256x256, 512 threads, 16 warps of 64x64 (4x4), KC=32, 3-stage
// cp.async, 1 CTA/SM (16 warps/SM). Crossbar: 1.25 wf/MMA (was 2.5).
// M padded to 90 tiles; epilogue stores guarded by r < BS_.
// ---------------------------------------------------------------------------
#define KCH     32
#define NCH     (E_ / KCH)      // 32
#define PG      80
#define BM      256
#define BN      256
#define TILE_F  (BM * PG)       // 20480 per operand tile
#define STAGE_F (2 * TILE_F)    // 40960 (A+B)
#define NSTG    3
#define NMT     ((BS_ + BM - 1) / BM)   // 90

__global__ __launch_bounds__(512, 1) void qkv_gemm_f16()
{
    extern __shared__ __align__(128) char sb[];
    const int z = blockIdx.z;
    const int bm = blockIdx.x * BM;
    const int bn = blockIdx.y * BN;
    const int tid = threadIdx.x;
    const int wid = tid >> 5;
    const int lane = tid & 31;

    const uint32_t sbase = smem_u32(sb);
    const int warp_m = (wid >> 2) * 64;
    const int warp_n = (wid & 3) * 64;

    // loader: thread t -> row t>>1 (0..255), 16 halfs at (t&1)*16
    const int lr = tid >> 1;
    const int lc = (tid & 1) * 16;
    const __half* gA = g_fp16 + (size_t)(bm + lr) * E_ + lc;   // overread past
    const __half* gB = g_fp16 + (size_t)BS_ * E_ + (size_t)z * EE_ + (size_t)(bn + lr) * E_ + lc;
    const uint32_t dRow = (uint32_t)lr * PG + (uint32_t)lc * 2;

    const uint32_t aRow = (uint32_t)(lane & 15);
    const uint32_t aOff = (uint32_t)((lane >> 4) * 16);
    const uint32_t bRow = (uint32_t)(((lane >> 4) << 3) + (lane & 7));
    const uint32_t bOff = (uint32_t)(((lane >> 3) & 1) * 16);

    float acc[4][8][4];
#pragma unroll
    for (int i = 0; i < 4; i++)
#pragma unroll
        for (int j = 0; j < 8; j++)
#pragma unroll
            for (int k = 0; k < 4; k++) acc[i][j][k] = 0.f;

    // prologue: chunks 0,1 -> stages 0,1
#pragma unroll
    for (int p = 0; p < 2; p++) {
        uint32_t dA = sbase + (uint32_t)p * STAGE_F + dRow;
        uint32_t dB = dA + TILE_F;
        const __half* sA = gA + p * KCH;
        const __half* sB = gB + p * KCH;
        CP16(dA, sA);
        CP16(dA + 16, sA + 8);
        CP16(dB, sB);
        CP16(dB + 16, sB + 8);
        CP_COMMIT();
    }

    int buf = 0;
    int nbuf = 2;
    for (int c = 0; c < NCH; c++) {
        CP_WAIT1();
        __syncthreads();

        if (c + 2 < NCH) {
            uint32_t dA = sbase + (uint32_t)nbuf * STAGE_F + dRow;
            uint32_t dB = dA + TILE_F;
            const __half* sA = gA + (c + 2) * KCH;
            const __half* sB = gB + (c + 2) * KCH;
            CP16(dA, sA);
            CP16(dA + 16, sA + 8);
            CP16(dB, sB);
            CP16(dB + 16, sB + 8);
        }
        CP_COMMIT();

        const uint32_t stA = sbase + (uint32_t)buf * STAGE_F;
        const uint32_t stB = stA + TILE_F;
#pragma unroll
        for (int s = 0; s < 2; s++) {
            uint32_t Af[4][4];
#pragma unroll
            for (int mt = 0; mt < 4; mt++) {
                uint32_t ad = stA + (uint32_t)(warp_m + mt * 16 + aRow) * PG + s * 32 + aOff;
                LDSM_X4(Af[mt][0], Af[mt][1], Af[mt][2], Af[mt][3], ad);
            }
#pragma unroll
            for (int np = 0; np < 4; np++) {
                uint32_t B0, B1, B2, B3;
                uint32_t bd = stB + (uint32_t)(warp_n + np * 16 + bRow) * PG + s * 32 + bOff;
                LDSM_X4(B0, B1, B2, B3, bd);
#pragma unroll
                for (int mt = 0; mt < 4; mt++) {
                    MMA_F16(acc[mt][np * 2 + 0], Af[mt][0], Af[mt][1], Af[mt][2], Af[mt][3], B0, B1);
                    MMA_F16(acc[mt][np * 2 + 1], Af[mt][0], Af[mt][1], Af[mt][2], Af[mt][3], B2, B3);
                }
            }
        }
        buf  = (buf  + 1 == NSTG) ? 0 : buf  + 1;
        nbuf = (nbuf + 1 == NSTG) ? 0 : nbuf + 1;
    }

    // epilogue: coalesced fp16 stores into [bh][s][d], guarded for M padding
    __half* O = (z == 0) ? g_Qh : ((z == 1) ? g_Kh : g_Vh);
#pragma unroll
    for (int mt = 0; mt < 4; mt++) {
        const int r0 = bm + warp_m + mt * 16 + (lane >> 2);
        const int r1 = r0 + 8;
        const int bb0 = r0 / S_, ss0 = r0 - bb0 * S_;
        const int bb1 = r1 / S_, ss1 = r1 - bb1 * S_;
#pragma unroll
        for (int nt = 0; nt < 8; nt++) {
            const int n = bn + warp_n + nt * 8 + ((lane & 3) * 2);
            const int h = n >> 6;
            const int d = n & 63;
            if (r0 < BS_) {
                size_t i0 = ((size_t)(bb0 * H_ + h) * SP_ + ss0) * D_ + d;
                *(uint32_t*)(O + i0) = pack_h2(acc[mt][nt][0], acc[mt][nt][1]);
            }
            if (r1 < BS_) {
                size_t i1 = ((size_t)(bb1 * H_ + h) * SP_ + ss1) * D_ + d;
                *(uint32_t*)(O + i1) = pack_h2(acc[mt][nt][2], acc[mt][nt][3]);
            }
        }
    }
}

// ---------------------------------------------------------------------------
// Kernel 2: attention (unchanged from R10). 384 threads = 12 warps.
// ---------------------------------------------------------------------------
#define QKP2  144
#define SQ_B2  (SP_ * QKP2)               // 27648
#define ATT_SMEM2 (2 * SQ_B2)             // 55296

__global__ __launch_bounds__(384) void attn_kernel()
{
    extern __shared__ __align__(128) char sm[];
    char* sK = sm;
    char* sV = sm + SQ_B2;

    const int bh = blockIdx.x;
    const int b  = bh >> 4;
    const int h  = bh & 15;
    const int tid = threadIdx.x;
    const int wid = tid >> 5;      // 0..11
    const int lane = tid & 31;
    const int mtl = wid;           // one m-tile per warp

    {
        const uint32_t sKb0 = smem_u32(sK);
        const uint32_t sVb0 = smem_u32(sV);
        const __half* kg = g_Kh + (size_t)bh * SP_ * D_;
        const __half* vg = g_Vh + (size_t)bh * SP_ * D_;
        for (int i = tid; i < SP_ * 8; i += 384) {
            int row = i >> 3, seg = i & 7;
            CP16(sKb0 + row * QKP2 + seg * 16, kg + i * 8);
            CP16(sVb0 + row * QKP2 + seg * 16, vg + i * 8);
        }
        CP_COMMIT();
        const uint32_t ones2 = 0x3C003C00u;
        for (int r = tid; r < SP_; r += 384)
            *(uint4*)(sV + r * QKP2 + 128) = make_uint4(ones2, ones2, ones2, ones2);
    }

    uint32_t QA[4][4];
    {
        const __half* qg = g_Qh + (size_t)bh * SP_ * D_
                         + (size_t)(mtl * 16 + (lane >> 2)) * D_ + (lane & 3) * 2;
#pragma unroll
        for (int s = 0; s < 4; s++) {
            QA[s][0] = *(const uint32_t*)(qg + s * 16);
            QA[s][1] = *(const uint32_t*)(qg + 8 * D_ + s * 16);
            QA[s][2] = *(const uint32_t*)(qg + s * 16 + 8);
            QA[s][3] = *(const uint32_t*)(qg + 8 * D_ + s * 16 + 8);
        }
    }
    CP_WAIT0();
    __syncthreads();

    const uint32_t sKb = smem_u32(sK);
    const uint32_t sVb = smem_u32(sV);

    const uint32_t bRow = (uint32_t)(((lane >> 4) << 3) + (lane & 7));
    const uint32_t bOff = (uint32_t)(((lane >> 3) & 1) * 16);
    const uint32_t vRow = (uint32_t)(((lane >> 3) & 1) * 8 + (lane & 7));
    const uint32_t vCol = (uint32_t)((lane >> 4) * 16);

    float acc[24][4];
#pragma unroll
    for (int t = 0; t < 24; t++)
#pragma unroll
        for (int k = 0; k < 4; k++) acc[t][k] = 0.f;

#pragma unroll
    for (int s = 0; s < 4; s++) {
#pragma unroll
        for (int np = 0; np < 12; np++) {
            uint32_t B0, B1, B2, B3;
            uint32_t bd = sKb + (uint32_t)(np * 16 + bRow) * QKP2 + s * 32 + bOff;
            LDSM_X4(B0, B1, B2, B3, bd);
            MMA_F16(acc[np * 2 + 0], QA[s][0], QA[s][1], QA[s][2], QA[s][3], B0, B1);
            MMA_F16(acc[np * 2 + 1], QA[s][0], QA[s][1], QA[s][2], QA[s][3], B2, B3);
        }
    }

    const int q0 = mtl * 16 + (lane >> 2);
    const int q1 = q0 + 8;
    const int c2 = (lane & 3) * 2;
    const float wl2 = (0.03125f / 179.0f) * 1.4426950408889634f;  // wsc*log2e

    uint32_t p0[24], p1[24];
#pragma unroll
    for (int t = 0; t < 23; t++) {
        const float d00 = (float)(q0 - (t * 8 + c2));
        const float d10 = (float)(q1 - (t * 8 + c2));
        const float w00 = wl2 * fabsf(d00);
        const float w01 = wl2 * fabsf(d00 - 1.0f);
        const float w10 = wl2 * fabsf(d10);
        const float w11 = wl2 * fabsf(d10 - 1.0f);
        uint32_t e0, e1;
        CVT_F16X2(e0, acc[t][1] * w01, acc[t][0] * w00);
        CVT_F16X2(e1, acc[t][3] * w11, acc[t][2] * w10);
        EX2_F16X2(p0[t], e0);
        EX2_F16X2(p1[t], e1);
    }
    {
        const uint32_t mask = pack_h2((c2 < 3) ? 1.f : 0.f, (c2 < 2) ? 1.f : 0.f);
        MUL_F16X2(p0[22], p0[22], mask);
        MUL_F16X2(p1[22], p1[22], mask);
    }
    p0[23] = 0u;  p1[23] = 0u;

    float o[8][4];
#pragma unroll
    for (int nt = 0; nt < 8; nt++)
#pragma unroll
        for (int k = 0; k < 4; k++) o[nt][k] = 0.f;
    float osum[4] = {0.f, 0.f, 0.f, 0.f};

#pragma unroll
    for (int s = 0; s < 12; s++) {
        const uint32_t a0 = p0[2 * s];
        const uint32_t a1 = p1[2 * s];
        const uint32_t a2 = p0[2 * s + 1];
        const uint32_t a3 = p1[2 * s + 1];
#pragma unroll
        for (int np = 0; np < 4; np++) {
            uint32_t B0, B1, B2, B3;
            uint32_t bd = sVb + (uint32_t)(s * 16 + vRow) * QKP2 + np * 32 + vCol;
            LDSM_X4_T(B0, B1, B2, B3, bd);
            MMA_F16(o[np * 2 + 0], a0, a1, a2, a3, B0, B1);
            MMA_F16(o[np * 2 + 1], a0, a1, a2, a3, B2, B3);
        }
        uint32_t S0b, S1b;
        uint32_t bd2 = sVb + (uint32_t)(s * 16 + (lane & 15)) * QKP2 + 128;
        LDSM_X2_T(S0b, S1b, bd2);
        MMA_F16(osum, a0, a1, a2, a3, S0b, S1b);
    }

    const float inv0 = 1.0f / osum[0];
    const float inv1 = 1.0f / osum[2];

#pragma unroll
    for (int nt = 0; nt < 8; nt++) {
        const int d = nt * 8 + c2;
        if (q0 < S_) {
            float* p = g_att + ((size_t)(b * S_ + q0)) * E_ + h * 64 + d;
            *(float2*)p = make_float2(o[nt][0] * inv0, o[nt][1] * inv0);
        }
        if (q1 < S_) {
            float* p = g_att + ((size_t)(b * S_ + q1)) * E_ + h * 64 + d;
            *(float2*)p = make_float2(o[nt][2] * inv1, o[nt][3] * inv1);
        }
    }
}

// ---------------------------------------------------------------------------
// Kernel 3: LayerNorm, warp-per-row (no smem, no barriers, MLP 8).
// ---------------------------------------------------------------------------
__global__ __launch_bounds__(256) void ln_kernel(
    const float* __restrict__ gamma,
    const float* __restrict__ beta,
    float* __restrict__ out)
{
    const int wid = threadIdx.x >> 5;
    const int lane = threadIdx.x & 31;
    const int row = blockIdx.x * 8 + wid;

    const float4* src = (const float4*)(g_att + (size_t)row * E_);
    float4 v[8];
#pragma unroll
    for (int seg = 0; seg < 8; seg++) v[seg] = src[seg * 32 + lane];

    float s = 0.f, s2 = 0.f;
#pragma unroll
    for (int seg = 0; seg < 8; seg++) {
        s  += v[seg].x + v[seg].y + v[seg].z + v[seg].w;
        s2 += v[seg].x * v[seg].x + v[seg].y * v[seg].y
            + v[seg].z * v[seg].z + v[seg].w * v[seg].w;
    }
#pragma unroll
    for (int o = 16; o > 0; o >>= 1) {
        s  += __shfl_xor_sync(0xffffffffu, s, o);
        s2 += __shfl_xor_sync(0xffffffffu, s2, o);
    }

    const float mu  = s * (1.0f / E_);
    const float var = s2 * (1.0f / E_) - mu * mu;
    const float inv = rsqrtf(var + 1e-5f);

    float4* dst = (float4*)(out + (size_t)row * E_);
#pragma unroll
    for (int seg = 0; seg < 8; seg++) {
        const float4 g  = ((const float4*)gamma)[seg * 32 + lane];
        const float4 bt = ((const float4*)beta)[seg * 32 + lane];
        float4 r;
        r.x = (v[seg].x - mu) * inv * g.x + bt.x;
        r.y = (v[seg].y - mu) * inv * g.y + bt.y;
        r.z = (v[seg].z - mu) * inv * g.z + bt.z;
        r.w = (v[seg].w - mu) * inv * g.w + bt.w;
        dst[seg * 32 + lane] = r;
    }
}

// ---------------------------------------------------------------------------
extern "C" void kernel_launch(void* const* d_in, const int* in_sizes, int n_in,
                              void* d_out, int out_size)
{
    const float* x     = (const float*)d_in[0];
    const float* Wq    = (const float*)d_in[1];
    const float* Wk    = (const float*)d_in[2];
    const float* Wv    = (const float*)d_in[3];
    const float* gamma = (const float*)d_in[4];
    const float* beta  = (const float*)d_in[5];
    float* out = (float*)d_out;

    const int gemm_smem = NSTG * STAGE_F;   // 122880
    cudaFuncSetAttribute(qkv_gemm_f16, cudaFuncAttributeMaxDynamicSharedMemorySize, gemm_smem);
    cudaFuncSetAttribute(attn_kernel, cudaFuncAttributeMaxDynamicSharedMemorySize, ATT_SMEM2);

    cvt_fp16<<<dim3((BS_ * E_ / 8 + 255) / 256, 4), 256>>>(x, Wq, Wk, Wv);
    qkv_gemm_f16<<<dim3(NMT, E_ / BN, 3), 512, gemm_smem>>>();
    attn_kernel<<<BH_, 384, ATT_SMEM2>>>();
    ln_kernel<<<BS_ / 8, 256>>>(gamma, beta, out);
}

// round 12
// speedup vs baseline: 2.0963x; 2.0963x over previous
#include <cuda_runtime.h>
#include <cuda_fp16.h>
#include <cstdint>
#include <math.h>

#define B_   128
#define S_   179
#define E_   1024
#define H_   16
#define D_   64
#define BS_  (B_ * S_)          // 22912
#define BH_  (B_ * H_)          // 2048
#define SP_  192                // padded sequence (12 x 16)
#define EE_  (E_ * E_)

// fp16 copies of inputs: [ x (BS_*E_) | Wq | Wk | Wv ]
__device__ __half g_fp16[(size_t)BS_ * E_ + 3 * EE_];
// projection outputs (fp16), all [bh][s][d]. Pad rows [179,192) stay zero.
__device__ __half g_Qh[BH_ * SP_ * D_];
__device__ __half g_Kh[BH_ * SP_ * D_];
__device__ __half g_Vh[BH_ * SP_ * D_];
__device__ float g_att[(size_t)BS_ * E_];

// ---------------------------------------------------------------------------
// helpers
// ---------------------------------------------------------------------------
__device__ __forceinline__ uint32_t smem_u32(const void* p) {
    uint32_t a;
    asm("{ .reg .u64 t; cvta.to.shared.u64 t, %1; cvt.u32.u64 %0, t; }" : "=r"(a) : "l"(p));
    return a;
}
__device__ __forceinline__ uint32_t pack_h2(float x, float y) {
    __half2 h = __floats2half2_rn(x, y);
    return *reinterpret_cast<uint32_t*>(&h);
}

#define LDSM_X4(r0, r1, r2, r3, addr)                                          \
    asm volatile("ldmatrix.sync.aligned.m8n8.x4.shared.b16 {%0,%1,%2,%3}, [%4];" \
                 : "=r"(r0), "=r"(r1), "=r"(r2), "=r"(r3) : "r"(addr))

#define LDSM_X4_T(r0, r1, r2, r3, addr)                                        \
    asm volatile("ldmatrix.sync.aligned.m8n8.x4.trans.shared.b16 {%0,%1,%2,%3}, [%4];" \
                 : "=r"(r0), "=r"(r1), "=r"(r2), "=r"(r3) : "r"(addr))

#define LDSM_X2_T(r0, r1, addr)                                                \
    asm volatile("ldmatrix.sync.aligned.m8n8.x2.trans.shared.b16 {%0,%1}, [%2];" \
                 : "=r"(r0), "=r"(r1) : "r"(addr))

#define MMA_F16(c, a0, a1, a2, a3, b0, b1)                                     \
    asm volatile("mma.sync.aligned.m16n8k16.row.col.f32.f16.f16.f32 "          \
        "{%0,%1,%2,%3}, {%4,%5,%6,%7}, {%8,%9}, {%0,%1,%2,%3};"                \
        : "+f"((c)[0]), "+f"((c)[1]), "+f"((c)[2]), "+f"((c)[3])               \
        : "r"(a0), "r"(a1), "r"(a2), "r"(a3), "r"(b0), "r"(b1))

#define CP16(dst, src)                                                         \
    asm volatile("cp.async.cg.shared.global [%0], [%1], 16;" :: "r"(dst), "l"(src) : "memory")
#define CP_COMMIT()  asm volatile("cp.async.commit_group;" ::: "memory")
#define CP_WAIT1()   asm volatile("cp.async.wait_group 1;" ::: "memory")
#define CP_WAIT0()   asm volatile("cp.async.wait_group 0;" ::: "memory")

// d = {hi, lo} as f16x2 (first PTX source -> upper half)
#define CVT_F16X2(d, hi, lo)                                                   \
    asm("cvt.rn.f16x2.f32 %0, %1, %2;" : "=r"(d) : "f"(hi), "f"(lo))
#define EX2_F16X2(d, s)                                                        \
    asm("ex2.approx.f16x2 %0, %1;" : "=r"(d) : "r"(s))
#define MUL_F16X2(d, a, b)                                                     \
    asm("mul.rn.f16x2 %0, %1, %2;" : "=r"(d) : "r"(a), "r"(b))

// ---------------------------------------------------------------------------
// Kernel 0: fp32 -> fp16 pre-convert. 2 float4 per thread (ILP).
// ---------------------------------------------------------------------------
__global__ __launch_bounds__(256) void cvt_fp16(
    const float* __restrict__ x,  const float* __restrict__ Wq,
    const float* __restrict__ Wk, const float* __restrict__ Wv)
{
    const int z = blockIdx.y;
    const float* src = (z == 0) ? x : ((z == 1) ? Wq : ((z == 2) ? Wk : Wv));
    const size_t cnt = (z == 0) ? (size_t)BS_ * E_ : (size_t)EE_;
    const size_t off = (z == 0) ? 0 : (size_t)BS_ * E_ + (size_t)(z - 1) * EE_;
    const size_t base = ((size_t)blockIdx.x * 512 + threadIdx.x) * 4;
#pragma unroll
    for (int r = 0; r < 2; r++) {
        const size_t i = base + (size_t)r * 1024;
        if (i < cnt) {
            float4 v = *(const float4*)(src + i);
            *(uint2*)(g_fp16 + off + i) = make_uint2(pack_h2(v.x, v.y), pack_h2(v.z, v.w));
        }
    }
}

// ---------------------------------------------------------------------------
// Kernel 1: QKV projection, fp16 MMA.  C = A @ W^T.
// CTA tile 128x256, 256 threads, 8 warps of 64x64 (2x4), KC=32, 3-stage
// cp.async, 1 CTA/SM. Crossbar 1.47 wf/MMA (R10: 2.5); regs ~168 < 255 cap.
// ---------------------------------------------------------------------------
#define KCH     32
#define NCH     (E_ / KCH)      // 32
#define PG      80
#define BM      128
#define BN      256
#define ATILE_F (BM * PG)       // 10240
#define BTILE_F (BN * PG)       // 20480
#define STAGE_F (ATILE_F + BTILE_F)  // 30720
#define NSTG    3

__global__ __launch_bounds__(256, 1) void qkv_gemm_f16()
{
    extern __shared__ __align__(128) char sb[];
    const int z = blockIdx.z;
    const int bm = blockIdx.x * BM;
    const int bn = blockIdx.y * BN;
    const int tid = threadIdx.x;
    const int wid = tid >> 5;
    const int lane = tid & 31;

    const uint32_t sbase = smem_u32(sb);
    const int warp_m = (wid >> 2) * 64;
    const int warp_n = (wid & 3) * 64;

    // loaders: A: thread t -> row t>>1, 16 halfs at (t&1)*16 (2 CP16)
    //          B: thread t -> row t,   32 halfs (4 CP16)
    const int lrA = tid >> 1;
    const int lcA = (tid & 1) * 16;
    const __half* gA = g_fp16 + (size_t)(bm + lrA) * E_ + lcA;
    const __half* gB = g_fp16 + (size_t)BS_ * E_ + (size_t)z * EE_ + (size_t)(bn + tid) * E_;
    const uint32_t dRowA = (uint32_t)lrA * PG + (uint32_t)lcA * 2;
    const uint32_t dRowB = (uint32_t)tid * PG;

    const uint32_t aRow = (uint32_t)(lane & 15);
    const uint32_t aOff = (uint32_t)((lane >> 4) * 16);
    const uint32_t bRow = (uint32_t)(((lane >> 4) << 3) + (lane & 7));
    const uint32_t bOff = (uint32_t)(((lane >> 3) & 1) * 16);

    float acc[4][8][4];
#pragma unroll
    for (int i = 0; i < 4; i++)
#pragma unroll
        for (int j = 0; j < 8; j++)
#pragma unroll
            for (int k = 0; k < 4; k++) acc[i][j][k] = 0.f;

    // prologue: chunks 0,1 -> stages 0,1
#pragma unroll
    for (int p = 0; p < 2; p++) {
        uint32_t dA = sbase + (uint32_t)p * STAGE_F + dRowA;
        uint32_t dB = sbase + (uint32_t)p * STAGE_F + ATILE_F + dRowB;
        const __half* sA = gA + p * KCH;
        const __half* sB = gB + p * KCH;
        CP16(dA, sA);
        CP16(dA + 16, sA + 8);
#pragma unroll
        for (int j = 0; j < 4; j++) CP16(dB + j * 16, sB + j * 8);
        CP_COMMIT();
    }

    int buf = 0;
    int nbuf = 2;
    for (int c = 0; c < NCH; c++) {
        CP_WAIT1();
        __syncthreads();

        if (c + 2 < NCH) {
            uint32_t dA = sbase + (uint32_t)nbuf * STAGE_F + dRowA;
            uint32_t dB = sbase + (uint32_t)nbuf * STAGE_F + ATILE_F + dRowB;
            const __half* sA = gA + (c + 2) * KCH;
            const __half* sB = gB + (c + 2) * KCH;
            CP16(dA, sA);
            CP16(dA + 16, sA + 8);
#pragma unroll
            for (int j = 0; j < 4; j++) CP16(dB + j * 16, sB + j * 8);
        }
        CP_COMMIT();

        const uint32_t stA = sbase + (uint32_t)buf * STAGE_F;
        const uint32_t stB = stA + ATILE_F;
#pragma unroll
        for (int s = 0; s < 2; s++) {
            uint32_t Af[4][4];
#pragma unroll
            for (int mt = 0; mt < 4; mt++) {
                uint32_t ad = stA + (uint32_t)(warp_m + mt * 16 + aRow) * PG + s * 32 + aOff;
                LDSM_X4(Af[mt][0], Af[mt][1], Af[mt][2], Af[mt][3], ad);
            }
#pragma unroll
            for (int np = 0; np < 4; np++) {
                uint32_t B0, B1, B2, B3;
                uint32_t bd = stB + (uint32_t)(warp_n + np * 16 + bRow) * PG + s * 32 + bOff;
                LDSM_X4(B0, B1, B2, B3, bd);
#pragma unroll
                for (int mt = 0; mt < 4; mt++) {
                    MMA_F16(acc[mt][np * 2 + 0], Af[mt][0], Af[mt][1], Af[mt][2], Af[mt][3], B0, B1);
                    MMA_F16(acc[mt][np * 2 + 1], Af[mt][0], Af[mt][1], Af[mt][2], Af[mt][3], B2, B3);
                }
            }
        }
        buf  = (buf  + 1 == NSTG) ? 0 : buf  + 1;
        nbuf = (nbuf + 1 == NSTG) ? 0 : nbuf + 1;
    }

    // epilogue: coalesced fp16 stores into [bh][s][d]
    __half* O = (z == 0) ? g_Qh : ((z == 1) ? g_Kh : g_Vh);
#pragma unroll
    for (int mt = 0; mt < 4; mt++) {
        const int r0 = bm + warp_m + mt * 16 + (lane >> 2);
        const int r1 = r0 + 8;
        const int bb0 = r0 / S_, ss0 = r0 - bb0 * S_;
        const int bb1 = r1 / S_, ss1 = r1 - bb1 * S_;
#pragma unroll
        for (int nt = 0; nt < 8; nt++) {
            const int n = bn + warp_n + nt * 8 + ((lane & 3) * 2);
            const int h = n >> 6;
            const int d = n & 63;
            size_t i0 = ((size_t)(bb0 * H_ + h) * SP_ + ss0) * D_ + d;
            size_t i1 = ((size_t)(bb1 * H_ + h) * SP_ + ss1) * D_ + d;
            *(uint32_t*)(O + i0) = pack_h2(acc[mt][nt][0], acc[mt][nt][1]);
            *(uint32_t*)(O + i1) = pack_h2(acc[mt][nt][2], acc[mt][nt][3]);
        }
    }
}

// ---------------------------------------------------------------------------
// Kernel 2: attention (unchanged from R10). 384 threads = 12 warps.
// ---------------------------------------------------------------------------
#define QKP2  144
#define SQ_B2  (SP_ * QKP2)               // 27648
#define ATT_SMEM2 (2 * SQ_B2)             // 55296

__global__ __launch_bounds__(384) void attn_kernel()
{
    extern __shared__ __align__(128) char sm[];
    char* sK = sm;
    char* sV = sm + SQ_B2;

    const int bh = blockIdx.x;
    const int b  = bh >> 4;
    const int h  = bh & 15;
    const int tid = threadIdx.x;
    const int wid = tid >> 5;      // 0..11
    const int lane = tid & 31;
    const int mtl = wid;           // one m-tile per warp

    {
        const uint32_t sKb0 = smem_u32(sK);
        const uint32_t sVb0 = smem_u32(sV);
        const __half* kg = g_Kh + (size_t)bh * SP_ * D_;
        const __half* vg = g_Vh + (size_t)bh * SP_ * D_;
        for (int i = tid; i < SP_ * 8; i += 384) {
            int row = i >> 3, seg = i & 7;
            CP16(sKb0 + row * QKP2 + seg * 16, kg + i * 8);
            CP16(sVb0 + row * QKP2 + seg * 16, vg + i * 8);
        }
        CP_COMMIT();
        const uint32_t ones2 = 0x3C003C00u;
        for (int r = tid; r < SP_; r += 384)
            *(uint4*)(sV + r * QKP2 + 128) = make_uint4(ones2, ones2, ones2, ones2);
    }

    uint32_t QA[4][4];
    {
        const __half* qg = g_Qh + (size_t)bh * SP_ * D_
                         + (size_t)(mtl * 16 + (lane >> 2)) * D_ + (lane & 3) * 2;
#pragma unroll
        for (int s = 0; s < 4; s++) {
            QA[s][0] = *(const uint32_t*)(qg + s * 16);
            QA[s][1] = *(const uint32_t*)(qg + 8 * D_ + s * 16);
            QA[s][2] = *(const uint32_t*)(qg + s * 16 + 8);
            QA[s][3] = *(const uint32_t*)(qg + 8 * D_ + s * 16 + 8);
        }
    }
    CP_WAIT0();
    __syncthreads();

    const uint32_t sKb = smem_u32(sK);
    const uint32_t sVb = smem_u32(sV);

    const uint32_t bRow = (uint32_t)(((lane >> 4) << 3) + (lane & 7));
    const uint32_t bOff = (uint32_t)(((lane >> 3) & 1) * 16);
    const uint32_t vRow = (uint32_t)(((lane >> 3) & 1) * 8 + (lane & 7));
    const uint32_t vCol = (uint32_t)((lane >> 4) * 16);

    float acc[24][4];
#pragma unroll
    for (int t = 0; t < 24; t++)
#pragma unroll
        for (int k = 0; k < 4; k++) acc[t][k] = 0.f;

#pragma unroll
    for (int s = 0; s < 4; s++) {
#pragma unroll
        for (int np = 0; np < 12; np++) {
            uint32_t B0, B1, B2, B3;
            uint32_t bd = sKb + (uint32_t)(np * 16 + bRow) * QKP2 + s * 32 + bOff;
            LDSM_X4(B0, B1, B2, B3, bd);
            MMA_F16(acc[np * 2 + 0], QA[s][0], QA[s][1], QA[s][2], QA[s][3], B0, B1);
            MMA_F16(acc[np * 2 + 1], QA[s][0], QA[s][1], QA[s][2], QA[s][3], B2, B3);
        }
    }

    const int q0 = mtl * 16 + (lane >> 2);
    const int q1 = q0 + 8;
    const int c2 = (lane & 3) * 2;
    const float wl2 = (0.03125f / 179.0f) * 1.4426950408889634f;  // wsc*log2e

    uint32_t p0[24], p1[24];
#pragma unroll
    for (int t = 0; t < 23; t++) {
        const float d00 = (float)(q0 - (t * 8 + c2));
        const float d10 = (float)(q1 - (t * 8 + c2));
        const float w00 = wl2 * fabsf(d00);
        const float w01 = wl2 * fabsf(d00 - 1.0f);
        const float w10 = wl2 * fabsf(d10);
        const float w11 = wl2 * fabsf(d10 - 1.0f);
        uint32_t e0, e1;
        CVT_F16X2(e0, acc[t][1] * w01, acc[t][0] * w00);
        CVT_F16X2(e1, acc[t][3] * w11, acc[t][2] * w10);
        EX2_F16X2(p0[t], e0);
        EX2_F16X2(p1[t], e1);
    }
    {
        const uint32_t mask = pack_h2((c2 < 3) ? 1.f : 0.f, (c2 < 2) ? 1.f : 0.f);
        MUL_F16X2(p0[22], p0[22], mask);
        MUL_F16X2(p1[22], p1[22], mask);
    }
    p0[23] = 0u;  p1[23] = 0u;

    float o[8][4];
#pragma unroll
    for (int nt = 0; nt < 8; nt++)
#pragma unroll
        for (int k = 0; k < 4; k++) o[nt][k] = 0.f;
    float osum[4] = {0.f, 0.f, 0.f, 0.f};

#pragma unroll
    for (int s = 0; s < 12; s++) {
        const uint32_t a0 = p0[2 * s];
        const uint32_t a1 = p1[2 * s];
        const uint32_t a2 = p0[2 * s + 1];
        const uint32_t a3 = p1[2 * s + 1];
#pragma unroll
        for (int np = 0; np < 4; np++) {
            uint32_t B0, B1, B2, B3;
            uint32_t bd = sVb + (uint32_t)(s * 16 + vRow) * QKP2 + np * 32 + vCol;
            LDSM_X4_T(B0, B1, B2, B3, bd);
            MMA_F16(o[np * 2 + 0], a0, a1, a2, a3, B0, B1);
            MMA_F16(o[np * 2 + 1], a0, a1, a2, a3, B2, B3);
        }
        uint32_t S0b, S1b;
        uint32_t bd2 = sVb + (uint32_t)(s * 16 + (lane & 15)) * QKP2 + 128;
        LDSM_X2_T(S0b, S1b, bd2);
        MMA_F16(osum, a0, a1, a2, a3, S0b, S1b);
    }

    const float inv0 = 1.0f / osum[0];
    const float inv1 = 1.0f / osum[2];

#pragma unroll
    for (int nt = 0; nt < 8; nt++) {
        const int d = nt * 8 + c2;
        if (q0 < S_) {
            float* p = g_att + ((size_t)(b * S_ + q0)) * E_ + h * 64 + d;
            *(float2*)p = make_float2(o[nt][0] * inv0, o[nt][1] * inv0);
        }
        if (q1 < S_) {
            float* p = g_att + ((size_t)(b * S_ + q1)) * E_ + h * 64 + d;
            *(float2*)p = make_float2(o[nt][2] * inv1, o[nt][3] * inv1);
        }
    }
}

// ---------------------------------------------------------------------------
// Kernel 3: LayerNorm, warp-per-row (no smem, no barriers, MLP 8).
// ---------------------------------------------------------------------------
__global__ __launch_bounds__(256) void ln_kernel(
    const float* __restrict__ gamma,
    const float* __restrict__ beta,
    float* __restrict__ out)
{
    const int wid = threadIdx.x >> 5;
    const int lane = threadIdx.x & 31;
    const int row = blockIdx.x * 8 + wid;

    const float4* src = (const float4*)(g_att + (size_t)row * E_);
    float4 v[8];
#pragma unroll
    for (int seg = 0; seg < 8; seg++) v[seg] = src[seg * 32 + lane];

    float s = 0.f, s2 = 0.f;
#pragma unroll
    for (int seg = 0; seg < 8; seg++) {
        s  += v[seg].x + v[seg].y + v[seg].z + v[seg].w;
        s2 += v[seg].x * v[seg].x + v[seg].y * v[seg].y
            + v[seg].z * v[seg].z + v[seg].w * v[seg].w;
    }
#pragma unroll
    for (int o = 16; o > 0; o >>= 1) {
        s  += __shfl_xor_sync(0xffffffffu, s, o);
        s2 += __shfl_xor_sync(0xffffffffu, s2, o);
    }

    const float mu  = s * (1.0f / E_);
    const float var = s2 * (1.0f / E_) - mu * mu;
    const float inv = rsqrtf(var + 1e-5f);

    float4* dst = (float4*)(out + (size_t)row * E_);
#pragma unroll
    for (int seg = 0; seg < 8; seg++) {
        const float4 g  = ((const float4*)gamma)[seg * 32 + lane];
        const float4 bt = ((const float4*)beta)[seg * 32 + lane];
        float4 r;
        r.x = (v[seg].x - mu) * inv * g.x + bt.x;
        r.y = (v[seg].y - mu) * inv * g.y + bt.y;
        r.z = (v[seg].z - mu) * inv * g.z + bt.z;
        r.w = (v[seg].w - mu) * inv * g.w + bt.w;
        dst[seg * 32 + lane] = r;
    }
}

// ---------------------------------------------------------------------------
extern "C" void kernel_launch(void* const* d_in, const int* in_sizes, int n_in,
                              void* d_out, int out_size)
{
    const float* x     = (const float*)d_in[0];
    const float* Wq    = (const float*)d_in[1];
    const float* Wk    = (const float*)d_in[2];
    const float* Wv    = (const float*)d_in[3];
    const float* gamma = (const float*)d_in[4];
    const float* beta  = (const float*)d_in[5];
    float* out = (float*)d_out;

    const int gemm_smem = NSTG * STAGE_F;   // 92160
    cudaFuncSetAttribute(qkv_gemm_f16, cudaFuncAttributeMaxDynamicSharedMemorySize, gemm_smem);
    cudaFuncSetAttribute(attn_kernel, cudaFuncAttributeMaxDynamicSharedMemorySize, ATT_SMEM2);

    cvt_fp16<<<dim3((BS_ * E_ / 8 + 255) / 256, 4), 256>>>(x, Wq, Wk, Wv);
    qkv_gemm_f16<<<dim3(BS_ / BM, E_ / BN, 3), 256, gemm_smem>>>();
    attn_kernel<<<BH_, 384, ATT_SMEM2>>>();
    ln_kernel<<<BS_ / 8, 256>>>(gamma, beta, out);
}

// round 13
// speedup vs baseline: 2.4141x; 1.1516x over previous
#include <cuda_runtime.h>
#include <cuda_fp16.h>
#include <cstdint>
#include <math.h>

#define B_   128
#define S_   179
#define E_   1024
#define H_   16
#define D_   64
#define BS_  (B_ * S_)          // 22912
#define BH_  (B_ * H_)          // 2048
#define SP_  192                // padded sequence (12 x 16)
#define EE_  (E_ * E_)

// fp16 copies of inputs: [ x (BS_*E_) | Wq | Wk | Wv ]
__device__ __half g_fp16[(size_t)BS_ * E_ + 3 * EE_];
// projection outputs (fp16), all [bh][s][d]. Pad rows [179,192) stay zero.
__device__ __half g_Qh[BH_ * SP_ * D_];
__device__ __half g_Kh[BH_ * SP_ * D_];
__device__ __half g_Vh[BH_ * SP_ * D_];
__device__ float g_att[(size_t)BS_ * E_];

// ---------------------------------------------------------------------------
// helpers
// ---------------------------------------------------------------------------
__device__ __forceinline__ uint32_t smem_u32(const void* p) {
    uint32_t a;
    asm("{ .reg .u64 t; cvta.to.shared.u64 t, %1; cvt.u32.u64 %0, t; }" : "=r"(a) : "l"(p));
    return a;
}
__device__ __forceinline__ uint32_t pack_h2(float x, float y) {
    __half2 h = __floats2half2_rn(x, y);
    return *reinterpret_cast<uint32_t*>(&h);
}

#define LDSM_X4(r0, r1, r2, r3, addr)                                          \
    asm volatile("ldmatrix.sync.aligned.m8n8.x4.shared.b16 {%0,%1,%2,%3}, [%4];" \
                 : "=r"(r0), "=r"(r1), "=r"(r2), "=r"(r3) : "r"(addr))

#define LDSM_X4_T(r0, r1, r2, r3, addr)                                        \
    asm volatile("ldmatrix.sync.aligned.m8n8.x4.trans.shared.b16 {%0,%1,%2,%3}, [%4];" \
                 : "=r"(r0), "=r"(r1), "=r"(r2), "=r"(r3) : "r"(addr))

#define LDSM_X2_T(r0, r1, addr)                                                \
    asm volatile("ldmatrix.sync.aligned.m8n8.x2.trans.shared.b16 {%0,%1}, [%2];" \
                 : "=r"(r0), "=r"(r1) : "r"(addr))

#define MMA_F16(c, a0, a1, a2, a3, b0, b1)                                     \
    asm volatile("mma.sync.aligned.m16n8k16.row.col.f32.f16.f16.f32 "          \
        "{%0,%1,%2,%3}, {%4,%5,%6,%7}, {%8,%9}, {%0,%1,%2,%3};"                \
        : "+f"((c)[0]), "+f"((c)[1]), "+f"((c)[2]), "+f"((c)[3])               \
        : "r"(a0), "r"(a1), "r"(a2), "r"(a3), "r"(b0), "r"(b1))

#define CP16(dst, src)                                                         \
    asm volatile("cp.async.cg.shared.global [%0], [%1], 16;" :: "r"(dst), "l"(src) : "memory")
#define CP_COMMIT()  asm volatile("cp.async.commit_group;" ::: "memory")
#define CP_WAIT1()   asm volatile("cp.async.wait_group 1;" ::: "memory")
#define CP_WAIT0()   asm volatile("cp.async.wait_group 0;" ::: "memory")

// d = {hi, lo} as f16x2 (first PTX source -> upper half)
#define CVT_F16X2(d, hi, lo)                                                   \
    asm("cvt.rn.f16x2.f32 %0, %1, %2;" : "=r"(d) : "f"(hi), "f"(lo))
#define EX2_F16X2(d, s)                                                        \
    asm("ex2.approx.f16x2 %0, %1;" : "=r"(d) : "r"(s))
#define MUL_F16X2(d, a, b)                                                     \
    asm("mul.rn.f16x2 %0, %1, %2;" : "=r"(d) : "r"(a), "r"(b))

// ---------------------------------------------------------------------------
// Kernel 0: fp32 -> fp16 pre-convert. 2 float4 per thread (ILP).
// ---------------------------------------------------------------------------
__global__ __launch_bounds__(256) void cvt_fp16(
    const float* __restrict__ x,  const float* __restrict__ Wq,
    const float* __restrict__ Wk, const float* __restrict__ Wv)
{
    const int z = blockIdx.y;
    const float* src = (z == 0) ? x : ((z == 1) ? Wq : ((z == 2) ? Wk : Wv));
    const size_t cnt = (z == 0) ? (size_t)BS_ * E_ : (size_t)EE_;
    const size_t off = (z == 0) ? 0 : (size_t)BS_ * E_ + (size_t)(z - 1) * EE_;
    const size_t base = ((size_t)blockIdx.x * 512 + threadIdx.x) * 4;
#pragma unroll
    for (int r = 0; r < 2; r++) {
        const size_t i = base + (size_t)r * 1024;
        if (i < cnt) {
            float4 v = *(const float4*)(src + i);
            *(uint2*)(g_fp16 + off + i) = make_uint2(pack_h2(v.x, v.y), pack_h2(v.z, v.w));
        }
    }
}

// ---------------------------------------------------------------------------
// Kernel 1: QKV projection, fp16 MMA.  C = A @ W^T.  (R10 config: 256 thr,
// 8 warps of 64x32, CTA 128x128, KC=32, 3-stage cp.async, 2 CTAs/SM.)
// ---------------------------------------------------------------------------
#define KCH     32
#define NCH     (E_ / KCH)      // 32
#define PG      80
#define TILE_F  (128 * PG)      // 10240 per operand tile
#define STAGE_F (2 * TILE_F)    // 20480 (A+B)
#define NSTG    3

__global__ __launch_bounds__(256, 2) void qkv_gemm_f16()
{
    extern __shared__ __align__(128) char sb[];
    const int z = blockIdx.z;
    const int bm = blockIdx.x * 128;
    const int bn = blockIdx.y * 128;
    const int tid = threadIdx.x;
    const int wid = tid >> 5;
    const int lane = tid & 31;

    const uint32_t sbase = smem_u32(sb);
    const int warp_m = (wid >> 2) * 64;
    const int warp_n = (wid & 3) * 32;

    const int lr = tid >> 1;
    const int lc = (tid & 1) * 16;
    const __half* gA = g_fp16 + (size_t)(bm + lr) * E_ + lc;
    const __half* gB = g_fp16 + (size_t)BS_ * E_ + (size_t)z * EE_ + (size_t)(bn + lr) * E_ + lc;
    const uint32_t dRow = (uint32_t)lr * PG + (uint32_t)lc * 2;

    const uint32_t aRow = (uint32_t)(lane & 15);
    const uint32_t aOff = (uint32_t)((lane >> 4) * 16);
    const uint32_t bRow = (uint32_t)(((lane >> 4) << 3) + (lane & 7));
    const uint32_t bOff = (uint32_t)(((lane >> 3) & 1) * 16);

    float acc[4][4][4];
#pragma unroll
    for (int i = 0; i < 4; i++)
#pragma unroll
        for (int j = 0; j < 4; j++)
#pragma unroll
            for (int k = 0; k < 4; k++) acc[i][j][k] = 0.f;

#pragma unroll
    for (int p = 0; p < 2; p++) {
        uint32_t dA = sbase + (uint32_t)p * STAGE_F + dRow;
        uint32_t dB = dA + TILE_F;
        const __half* sA = gA + p * KCH;
        const __half* sB = gB + p * KCH;
#pragma unroll
        for (int j = 0; j < 2; j++) {
            CP16(dA + j * 16, sA + j * 8);
            CP16(dB + j * 16, sB + j * 8);
        }
        CP_COMMIT();
    }

    int buf = 0;
    int nbuf = 2;
    for (int c = 0; c < NCH; c++) {
        CP_WAIT1();
        __syncthreads();

        if (c + 2 < NCH) {
            uint32_t dA = sbase + (uint32_t)nbuf * STAGE_F + dRow;
            uint32_t dB = dA + TILE_F;
            const __half* sA = gA + (c + 2) * KCH;
            const __half* sB = gB + (c + 2) * KCH;
#pragma unroll
            for (int j = 0; j < 2; j++) {
                CP16(dA + j * 16, sA + j * 8);
                CP16(dB + j * 16, sB + j * 8);
            }
        }
        CP_COMMIT();

        const uint32_t stA = sbase + (uint32_t)buf * STAGE_F;
        const uint32_t stB = stA + TILE_F;
#pragma unroll
        for (int s = 0; s < 2; s++) {
            uint32_t Af[4][4];
#pragma unroll
            for (int mt = 0; mt < 4; mt++) {
                uint32_t ad = stA + (uint32_t)(warp_m + mt * 16 + aRow) * PG + s * 32 + aOff;
                LDSM_X4(Af[mt][0], Af[mt][1], Af[mt][2], Af[mt][3], ad);
            }
#pragma unroll
            for (int np = 0; np < 2; np++) {
                uint32_t B0, B1, B2, B3;
                uint32_t bd = stB + (uint32_t)(warp_n + np * 16 + bRow) * PG + s * 32 + bOff;
                LDSM_X4(B0, B1, B2, B3, bd);
#pragma unroll
                for (int mt = 0; mt < 4; mt++) {
                    MMA_F16(acc[mt][np * 2 + 0], Af[mt][0], Af[mt][1], Af[mt][2], Af[mt][3], B0, B1);
                    MMA_F16(acc[mt][np * 2 + 1], Af[mt][0], Af[mt][1], Af[mt][2], Af[mt][3], B2, B3);
                }
            }
        }
        buf  = (buf  + 1 == NSTG) ? 0 : buf  + 1;
        nbuf = (nbuf + 1 == NSTG) ? 0 : nbuf + 1;
    }

    __half* O = (z == 0) ? g_Qh : ((z == 1) ? g_Kh : g_Vh);
#pragma unroll
    for (int mt = 0; mt < 4; mt++) {
        const int r0 = bm + warp_m + mt * 16 + (lane >> 2);
        const int r1 = r0 + 8;
        const int bb0 = r0 / S_, ss0 = r0 - bb0 * S_;
        const int bb1 = r1 / S_, ss1 = r1 - bb1 * S_;
#pragma unroll
        for (int nt = 0; nt < 4; nt++) {
            const int n = bn + warp_n + nt * 8 + ((lane & 3) * 2);
            const int h = n >> 6;
            const int d = n & 63;
            size_t i0 = ((size_t)(bb0 * H_ + h) * SP_ + ss0) * D_ + d;
            size_t i1 = ((size_t)(bb1 * H_ + h) * SP_ + ss1) * D_ + d;
            *(uint32_t*)(O + i0) = pack_h2(acc[mt][nt][0], acc[mt][nt][1]);
            *(uint32_t*)(O + i1) = pack_h2(acc[mt][nt][2], acc[mt][nt][3]);
        }
    }
}

// ---------------------------------------------------------------------------
// Kernel 2: attention, 384 threads = 12 warps, one m-tile per warp.
// K streamed in 2 chunks of 96 keys (softmax is linear once max-subtraction
// is gone) -> peak regs ~150 < 170 cap, no spills.
// ---------------------------------------------------------------------------
#define QKP2  144
#define SQ_B2  (SP_ * QKP2)               // 27648
#define ATT_SMEM2 (2 * SQ_B2)             // 55296

__global__ __launch_bounds__(384) void attn_kernel()
{
    extern __shared__ __align__(128) char sm[];
    char* sK = sm;
    char* sV = sm + SQ_B2;

    const int bh = blockIdx.x;
    const int b  = bh >> 4;
    const int h  = bh & 15;
    const int tid = threadIdx.x;
    const int wid = tid >> 5;      // 0..11
    const int lane = tid & 31;
    const int mtl = wid;           // one m-tile per warp

    {
        const uint32_t sKb0 = smem_u32(sK);
        const uint32_t sVb0 = smem_u32(sV);
        const __half* kg = g_Kh + (size_t)bh * SP_ * D_;
        const __half* vg = g_Vh + (size_t)bh * SP_ * D_;
        for (int i = tid; i < SP_ * 8; i += 384) {
            int row = i >> 3, seg = i & 7;
            CP16(sKb0 + row * QKP2 + seg * 16, kg + i * 8);
            CP16(sVb0 + row * QKP2 + seg * 16, vg + i * 8);
        }
        CP_COMMIT();
        const uint32_t ones2 = 0x3C003C00u;
        for (int r = tid; r < SP_; r += 384)
            *(uint4*)(sV + r * QKP2 + 128) = make_uint4(ones2, ones2, ones2, ones2);
    }

    uint32_t QA[4][4];
    {
        const __half* qg = g_Qh + (size_t)bh * SP_ * D_
                         + (size_t)(mtl * 16 + (lane >> 2)) * D_ + (lane & 3) * 2;
#pragma unroll
        for (int s = 0; s < 4; s++) {
            QA[s][0] = *(const uint32_t*)(qg + s * 16);
            QA[s][1] = *(const uint32_t*)(qg + 8 * D_ + s * 16);
            QA[s][2] = *(const uint32_t*)(qg + s * 16 + 8);
            QA[s][3] = *(const uint32_t*)(qg + 8 * D_ + s * 16 + 8);
        }
    }
    CP_WAIT0();
    __syncthreads();

    const uint32_t sKb = smem_u32(sK);
    const uint32_t sVb = smem_u32(sV);

    const uint32_t bRow = (uint32_t)(((lane >> 4) << 3) + (lane & 7));
    const uint32_t bOff = (uint32_t)(((lane >> 3) & 1) * 16);
    const uint32_t vRow = (uint32_t)(((lane >> 3) & 1) * 8 + (lane & 7));
    const uint32_t vCol = (uint32_t)((lane >> 4) * 16);

    const int q0 = mtl * 16 + (lane >> 2);
    const int c2 = (lane & 3) * 2;
    const float wl2 = (0.03125f / 179.0f) * 1.4426950408889634f;  // wsc*log2e

    float o[8][4];
#pragma unroll
    for (int nt = 0; nt < 8; nt++)
#pragma unroll
        for (int k = 0; k < 4; k++) o[nt][k] = 0.f;
    float osum[4] = {0.f, 0.f, 0.f, 0.f};

#pragma unroll
    for (int kc = 0; kc < 2; kc++) {
        // ---- QK^T for 96 keys
        float acc[12][4];
#pragma unroll
        for (int t = 0; t < 12; t++)
#pragma unroll
            for (int k = 0; k < 4; k++) acc[t][k] = 0.f;

#pragma unroll
        for (int s = 0; s < 4; s++) {
#pragma unroll
            for (int np = 0; np < 6; np++) {
                uint32_t B0, B1, B2, B3;
                uint32_t bd = sKb + (uint32_t)((kc * 6 + np) * 16 + bRow) * QKP2 + s * 32 + bOff;
                LDSM_X4(B0, B1, B2, B3, bd);
                MMA_F16(acc[np * 2 + 0], QA[s][0], QA[s][1], QA[s][2], QA[s][3], B0, B1);
                MMA_F16(acc[np * 2 + 1], QA[s][0], QA[s][1], QA[s][2], QA[s][3], B2, B3);
            }
        }

        // ---- bias + exp -> packed fp16 P
        uint32_t p0[12], p1[12];
#pragma unroll
        for (int t = 0; t < 12; t++) {
            const int g = kc * 12 + t;
            if (g >= 23) { p0[t] = 0u; p1[t] = 0u; continue; }
            const float d00 = (float)(q0 - (g * 8 + c2));
            const float d10 = d00 + 8.0f;
            const float w00 = wl2 * fabsf(d00);
            const float w01 = wl2 * fabsf(d00 - 1.0f);
            const float w10 = wl2 * fabsf(d10);
            const float w11 = wl2 * fabsf(d10 - 1.0f);
            uint32_t e0, e1;
            CVT_F16X2(e0, acc[t][1] * w01, acc[t][0] * w00);
            CVT_F16X2(e1, acc[t][3] * w11, acc[t][2] * w10);
            EX2_F16X2(p0[t], e0);
            EX2_F16X2(p1[t], e1);
        }
        if (kc == 1) {  // tile g=22 (local t=10): keys 176..183, zero k>=179
            const uint32_t mask = pack_h2((c2 < 3) ? 1.f : 0.f, (c2 < 2) ? 1.f : 0.f);
            MUL_F16X2(p0[10], p0[10], mask);
            MUL_F16X2(p1[10], p1[10], mask);
        }

        // ---- PV + ones-column sums (accumulate across chunks)
#pragma unroll
        for (int s2 = 0; s2 < 6; s2++) {
            const int sg = kc * 6 + s2;
            const uint32_t a0 = p0[2 * s2];
            const uint32_t a1 = p1[2 * s2];
            const uint32_t a2 = p0[2 * s2 + 1];
            const uint32_t a3 = p1[2 * s2 + 1];
#pragma unroll
            for (int np = 0; np < 4; np++) {
                uint32_t B0, B1, B2, B3;
                uint32_t bd = sVb + (uint32_t)(sg * 16 + vRow) * QKP2 + np * 32 + vCol;
                LDSM_X4_T(B0, B1, B2, B3, bd);
                MMA_F16(o[np * 2 + 0], a0, a1, a2, a3, B0, B1);
                MMA_F16(o[np * 2 + 1], a0, a1, a2, a3, B2, B3);
            }
            uint32_t S0b, S1b;
            uint32_t bd2 = sVb + (uint32_t)(sg * 16 + (lane & 15)) * QKP2 + 128;
            LDSM_X2_T(S0b, S1b, bd2);
            MMA_F16(osum, a0, a1, a2, a3, S0b, S1b);
        }
    }

    const int q1 = q0 + 8;
    const float inv0 = 1.0f / osum[0];
    const float inv1 = 1.0f / osum[2];

#pragma unroll
    for (int nt = 0; nt < 8; nt++) {
        const int d = nt * 8 + c2;
        if (q0 < S_) {
            float* p = g_att + ((size_t)(b * S_ + q0)) * E_ + h * 64 + d;
            *(float2*)p = make_float2(o[nt][0] * inv0, o[nt][1] * inv0);
        }
        if (q1 < S_) {
            float* p = g_att + ((size_t)(b * S_ + q1)) * E_ + h * 64 + d;
            *(float2*)p = make_float2(o[nt][2] * inv1, o[nt][3] * inv1);
        }
    }
}

// ---------------------------------------------------------------------------
// Kernel 3: LayerNorm, warp-per-row (no smem, no barriers, MLP 8).
// ---------------------------------------------------------------------------
__global__ __launch_bounds__(256) void ln_kernel(
    const float* __restrict__ gamma,
    const float* __restrict__ beta,
    float* __restrict__ out)
{
    const int wid = threadIdx.x >> 5;
    const int lane = threadIdx.x & 31;
    const int row = blockIdx.x * 8 + wid;

    const float4* src = (const float4*)(g_att + (size_t)row * E_);
    float4 v[8];
#pragma unroll
    for (int seg = 0; seg < 8; seg++) v[seg] = src[seg * 32 + lane];

    float s = 0.f, s2 = 0.f;
#pragma unroll
    for (int seg = 0; seg < 8; seg++) {
        s  += v[seg].x + v[seg].y + v[seg].z + v[seg].w;
        s2 += v[seg].x * v[seg].x + v[seg].y * v[seg].y
            + v[seg].z * v[seg].z + v[seg].w * v[seg].w;
    }
#pragma unroll
    for (int o = 16; o > 0; o >>= 1) {
        s  += __shfl_xor_sync(0xffffffffu, s, o);
        s2 += __shfl_xor_sync(0xffffffffu, s2, o);
    }

    const float mu  = s * (1.0f / E_);
    const float var = s2 * (1.0f / E_) - mu * mu;
    const float inv = rsqrtf(var + 1e-5f);

    float4* dst = (float4*)(out + (size_t)row * E_);
#pragma unroll
    for (int seg = 0; seg < 8; seg++) {
        const float4 g  = ((const float4*)gamma)[seg * 32 + lane];
        const float4 bt = ((const float4*)beta)[seg * 32 + lane];
        float4 r;
        r.x = (v[seg].x - mu) * inv * g.x + bt.x;
        r.y = (v[seg].y - mu) * inv * g.y + bt.y;
        r.z = (v[seg].z - mu) * inv * g.z + bt.z;
        r.w = (v[seg].w - mu) * inv * g.w + bt.w;
        dst[seg * 32 + lane] = r;
    }
}

// ---------------------------------------------------------------------------
extern "C" void kernel_launch(void* const* d_in, const int* in_sizes, int n_in,
                              void* d_out, int out_size)
{
    const float* x     = (const float*)d_in[0];
    const float* Wq    = (const float*)d_in[1];
    const float* Wk    = (const float*)d_in[2];
    const float* Wv    = (const float*)d_in[3];
    const float* gamma = (const float*)d_in[4];
    const float* beta  = (const float*)d_in[5];
    float* out = (float*)d_out;

    const int gemm_smem = NSTG * STAGE_F;   // 61440
    cudaFuncSetAttribute(qkv_gemm_f16, cudaFuncAttributeMaxDynamicSharedMemorySize, gemm_smem);
    cudaFuncSetAttribute(attn_kernel, cudaFuncAttributeMaxDynamicSharedMemorySize, ATT_SMEM2);

    cvt_fp16<<<dim3((BS_ * E_ / 8 + 255) / 256, 4), 256>>>(x, Wq, Wk, Wv);
    qkv_gemm_f16<<<dim3(BS_ / 128, E_ / 128, 3), 256, gemm_smem>>>();
    attn_kernel<<<BH_, 384, ATT_SMEM2>>>();
    ln_kernel<<<BS_ / 8, 256>>>(gamma, beta, out);
}